// round 1
// baseline (speedup 1.0000x reference)
#include <cuda_runtime.h>
#include <math.h>

#define B    32
#define S    512
#define DIM  1024
#define HID  4096
#define E    8
#define TOPK 2
#define CAP  8           // capacity = (B*TOPK)/E * 1.0 = 8
#define NPAIR (B*TOPK)   // 64

// ---------------- scratch (device globals; no allocations allowed) ----------
__device__ float g_ri[B * DIM];
__device__ int   g_sample[E * CAP];
__device__ float g_gate[E * CAP];
__device__ int   g_count[E];
// H activations: up to 64 pairs x 512 tokens x 4096 hidden (fp32) = 536 MB
__device__ float g_H[(size_t)E * CAP * S * HID];

// ---------------- kernel 1: ri = mean over sequence ------------------------
__global__ void ri_kernel(const float* __restrict__ rin) {
    int idx = blockIdx.x * blockDim.x + threadIdx.x;   // b*DIM + d
    if (idx >= B * DIM) return;
    int b = idx / DIM, d = idx % DIM;
    const float* p = rin + (size_t)b * S * DIM + d;
    float acc = 0.f;
    #pragma unroll 8
    for (int s = 0; s < S; ++s) acc += p[(size_t)s * DIM];
    g_ri[idx] = acc * (1.0f / S);
}

// ---------------- kernel 2: router + top-2 + capacity drop -----------------
__global__ void router_kernel(const float* __restrict__ noise,
                              const float* __restrict__ Wg, const float* __restrict__ bg,
                              const float* __restrict__ Wn, const float* __restrict__ bn) {
    __shared__ float s_noisy[B][E];
    __shared__ int   s_fe[NPAIR];
    __shared__ float s_fg[NPAIR];
    int t = threadIdx.x;
    if (t < B * E) {
        int b = t / E, e = t % E;
        const float* ri = g_ri + b * DIM;
        float lg = 0.f, ln = 0.f;
        for (int d = 0; d < DIM; ++d) {
            float r = ri[d];
            lg = fmaf(r, Wg[d * E + e], lg);
            ln = fmaf(r, Wn[d * E + e], ln);
        }
        lg += bg[e]; ln += bn[e];
        // stable softplus
        float sp = (ln > 20.f) ? ln : log1pf(expf(ln));
        s_noisy[b][e] = lg + noise[b * E + e] * sp;
    }
    __syncthreads();
    if (t < B) {
        // top-2 with JAX tie semantics (first index wins via strict >)
        float v1 = -INFINITY; int i1 = -1;
        for (int e = 0; e < E; ++e) { float v = s_noisy[t][e]; if (v > v1) { v1 = v; i1 = e; } }
        float v2 = -INFINITY; int i2 = -1;
        for (int e = 0; e < E; ++e) { if (e == i1) continue; float v = s_noisy[t][e]; if (v > v2) { v2 = v; i2 = e; } }
        float g1 = 1.f / (1.f + expf(v2 - v1));  // softmax over (v1 >= v2)
        float g2 = 1.f - g1;
        s_fe[t * TOPK + 0] = i1; s_fg[t * TOPK + 0] = g1;
        s_fe[t * TOPK + 1] = i2; s_fg[t * TOPK + 1] = g2;
    }
    __syncthreads();
    if (t == 0) {
        int cnt[E];
        #pragma unroll
        for (int e = 0; e < E; ++e) cnt[e] = 0;
        // stable-sort capacity: first CAP pairs per expert in flat-index order
        for (int p = 0; p < NPAIR; ++p) {
            int e = s_fe[p];
            int c = cnt[e]++;
            if (c < CAP) {
                g_sample[e * CAP + c] = p / TOPK;
                g_gate[e * CAP + c]   = s_fg[p];
            }
        }
        #pragma unroll
        for (int e = 0; e < E; ++e) g_count[e] = (cnt[e] < CAP) ? cnt[e] : CAP;
    }
}

// ---------------- zero output ----------------------------------------------
__global__ void zero_kernel(float4* __restrict__ out) {
    const size_t n4 = (size_t)B * S * DIM / 4;
    size_t i = (size_t)blockIdx.x * blockDim.x + threadIdx.x;
    size_t stride = (size_t)gridDim.x * blockDim.x;
    for (; i < n4; i += stride) out[i] = make_float4(0.f, 0.f, 0.f, 0.f);
}

// ---------------- GEMM1: H = GELU(X_e @ W1[e] + b1[e]) ---------------------
// Block tile 128x128x8, 256 threads, 8x8 per thread. M rows are contiguous
// tokens within one (expert,slot) pair (512 % 128 == 0).
__global__ void __launch_bounds__(256) gemm1_kernel(const float* __restrict__ x,
                                                    const float* __restrict__ W1,
                                                    const float* __restrict__ b1) {
    const int e    = blockIdx.z;
    const int m0   = blockIdx.y * 128;
    const int slot = m0 / S;
    if (slot >= g_count[e]) return;
    const int n0     = blockIdx.x * 128;
    const int token0 = m0 % S;
    const int sample = g_sample[e * CAP + slot];

    const float* A  = x  + ((size_t)sample * S + token0) * DIM;     // lda = DIM
    const float* Bm = W1 + (size_t)e * DIM * HID + n0;              // ldb = HID

    __shared__ float As[8][128];
    __shared__ float Bs[8][128];

    const int tid  = threadIdx.x;
    const int arow = tid >> 1;            // 0..127
    const int akq  = (tid & 1) * 4;       // 0 or 4
    const int brow = tid >> 5;            // 0..7
    const int bcol = (tid & 31) * 4;      // 0..124
    const int row0 = (tid >> 4) * 8;
    const int col0 = (tid & 15) * 8;

    float acc[8][8];
    #pragma unroll
    for (int i = 0; i < 8; ++i)
        #pragma unroll
        for (int j = 0; j < 8; ++j) acc[i][j] = 0.f;

    for (int k0 = 0; k0 < DIM; k0 += 8) {
        float4 av = *reinterpret_cast<const float4*>(A + (size_t)arow * DIM + k0 + akq);
        As[akq + 0][arow] = av.x; As[akq + 1][arow] = av.y;
        As[akq + 2][arow] = av.z; As[akq + 3][arow] = av.w;
        float4 bv = *reinterpret_cast<const float4*>(Bm + (size_t)(k0 + brow) * HID + bcol);
        *reinterpret_cast<float4*>(&Bs[brow][bcol]) = bv;
        __syncthreads();
        #pragma unroll
        for (int kk = 0; kk < 8; ++kk) {
            float4 ta0 = *reinterpret_cast<const float4*>(&As[kk][row0]);
            float4 ta1 = *reinterpret_cast<const float4*>(&As[kk][row0 + 4]);
            float4 tb0 = *reinterpret_cast<const float4*>(&Bs[kk][col0]);
            float4 tb1 = *reinterpret_cast<const float4*>(&Bs[kk][col0 + 4]);
            float a[8] = {ta0.x, ta0.y, ta0.z, ta0.w, ta1.x, ta1.y, ta1.z, ta1.w};
            float b[8] = {tb0.x, tb0.y, tb0.z, tb0.w, tb1.x, tb1.y, tb1.z, tb1.w};
            #pragma unroll
            for (int i = 0; i < 8; ++i)
                #pragma unroll
                for (int j = 0; j < 8; ++j)
                    acc[i][j] = fmaf(a[i], b[j], acc[i][j]);
        }
        __syncthreads();
    }

    float bias_s[8];
    #pragma unroll
    for (int j = 0; j < 8; ++j) bias_s[j] = b1[(size_t)e * HID + n0 + col0 + j];

    float* H = g_H + ((size_t)(e * CAP + slot) * S + token0) * HID + n0;
    #pragma unroll
    for (int i = 0; i < 8; ++i) {
        float tmp[8];
        #pragma unroll
        for (int j = 0; j < 8; ++j) {
            float v = acc[i][j] + bias_s[j];
            tmp[j] = 0.5f * v * (1.0f + erff(v * 0.70710678118654752f));  // exact GELU
        }
        float* dst = H + (size_t)(row0 + i) * HID + col0;
        *reinterpret_cast<float4*>(dst)     = make_float4(tmp[0], tmp[1], tmp[2], tmp[3]);
        *reinterpret_cast<float4*>(dst + 4) = make_float4(tmp[4], tmp[5], tmp[6], tmp[7]);
    }
}

// ---------------- GEMM2: out += gate * (H @ W2[e] + b2[e]) -----------------
__global__ void __launch_bounds__(256) gemm2_kernel(const float* __restrict__ W2,
                                                    const float* __restrict__ b2,
                                                    float* __restrict__ out) {
    const int e    = blockIdx.z;
    const int m0   = blockIdx.y * 128;
    const int slot = m0 / S;
    if (slot >= g_count[e]) return;
    const int n0     = blockIdx.x * 128;
    const int token0 = m0 % S;
    const int sample = g_sample[e * CAP + slot];
    const float gate = g_gate[e * CAP + slot];

    const float* A  = g_H + ((size_t)(e * CAP + slot) * S + token0) * HID;  // lda = HID
    const float* Bm = W2  + (size_t)e * HID * DIM + n0;                      // ldb = DIM

    __shared__ float As[8][128];
    __shared__ float Bs[8][128];

    const int tid  = threadIdx.x;
    const int arow = tid >> 1;
    const int akq  = (tid & 1) * 4;
    const int brow = tid >> 5;
    const int bcol = (tid & 31) * 4;
    const int row0 = (tid >> 4) * 8;
    const int col0 = (tid & 15) * 8;

    float acc[8][8];
    #pragma unroll
    for (int i = 0; i < 8; ++i)
        #pragma unroll
        for (int j = 0; j < 8; ++j) acc[i][j] = 0.f;

    for (int k0 = 0; k0 < HID; k0 += 8) {
        float4 av = *reinterpret_cast<const float4*>(A + (size_t)arow * HID + k0 + akq);
        As[akq + 0][arow] = av.x; As[akq + 1][arow] = av.y;
        As[akq + 2][arow] = av.z; As[akq + 3][arow] = av.w;
        float4 bv = *reinterpret_cast<const float4*>(Bm + (size_t)(k0 + brow) * DIM + bcol);
        *reinterpret_cast<float4*>(&Bs[brow][bcol]) = bv;
        __syncthreads();
        #pragma unroll
        for (int kk = 0; kk < 8; ++kk) {
            float4 ta0 = *reinterpret_cast<const float4*>(&As[kk][row0]);
            float4 ta1 = *reinterpret_cast<const float4*>(&As[kk][row0 + 4]);
            float4 tb0 = *reinterpret_cast<const float4*>(&Bs[kk][col0]);
            float4 tb1 = *reinterpret_cast<const float4*>(&Bs[kk][col0 + 4]);
            float a[8] = {ta0.x, ta0.y, ta0.z, ta0.w, ta1.x, ta1.y, ta1.z, ta1.w};
            float b[8] = {tb0.x, tb0.y, tb0.z, tb0.w, tb1.x, tb1.y, tb1.z, tb1.w};
            #pragma unroll
            for (int i = 0; i < 8; ++i)
                #pragma unroll
                for (int j = 0; j < 8; ++j)
                    acc[i][j] = fmaf(a[i], b[j], acc[i][j]);
        }
        __syncthreads();
    }

    float bias_s[8];
    #pragma unroll
    for (int j = 0; j < 8; ++j) bias_s[j] = b2[(size_t)e * DIM + n0 + col0 + j];

    #pragma unroll
    for (int i = 0; i < 8; ++i) {
        float* dst = out + ((size_t)sample * S + token0 + row0 + i) * DIM + n0 + col0;
        #pragma unroll
        for (int j = 0; j < 8; ++j) {
            float v = (acc[i][j] + bias_s[j]) * gate;
            atomicAdd(dst + j, v);   // <=2 adds per element -> deterministic
        }
    }
}

// ---------------- launch ----------------------------------------------------
extern "C" void kernel_launch(void* const* d_in, const int* in_sizes, int n_in,
                              void* d_out, int out_size) {
    const float* rin   = (const float*)d_in[0];
    const float* x     = (const float*)d_in[1];
    const float* noise = (const float*)d_in[2];
    const float* Wg    = (const float*)d_in[3];
    const float* bg    = (const float*)d_in[4];
    const float* Wn    = (const float*)d_in[5];
    const float* bn    = (const float*)d_in[6];
    const float* W1    = (const float*)d_in[7];
    const float* b1    = (const float*)d_in[8];
    const float* W2    = (const float*)d_in[9];
    const float* b2    = (const float*)d_in[10];
    float* out = (float*)d_out;

    ri_kernel<<<(B * DIM + 255) / 256, 256>>>(rin);
    router_kernel<<<1, 256>>>(noise, Wg, bg, Wn, bn);
    zero_kernel<<<4096, 256>>>(reinterpret_cast<float4*>(out));
    gemm1_kernel<<<dim3(HID / 128, CAP * S / 128, E), 256>>>(x, W1, b1);
    gemm2_kernel<<<dim3(DIM / 128, CAP * S / 128, E), 256>>>(W2, b2, out);
}

// round 3
// speedup vs baseline: 2.2213x; 2.2213x over previous
#include <cuda_runtime.h>
#include <cuda_bf16.h>
#include <math.h>
#include <stdint.h>

#define B    32
#define S    512
#define DIM  1024
#define HID  4096
#define E    8
#define TOPK 2
#define CAP  8
#define NPAIR (B*TOPK)

#define KC   32                 // K chunk (bf16 elems)
#define A_STRIDE 80             // bytes per A row in smem (32*2 padded to 80)
#define B_STRIDE 272            // bytes per B row in smem (128*2 padded to 272)
#define A_MAT   10240           // 128 rows * 80B
#define B_MAT   8704            // 32 rows * 272B
#define STAGE   37888           // Ah + Al + Bh + Bl
#define SMEM_DYN (2 * STAGE)

// ---------------- device scratch -------------------------------------------
__device__ float g_ri[B * DIM];
__device__ int   g_sample[E * CAP];
__device__ float g_gate[E * CAP];
__device__ int   g_count[E];
__device__ __nv_bfloat16 g_xc_hi[(size_t)B * S * DIM];
__device__ __nv_bfloat16 g_xc_lo[(size_t)B * S * DIM];
__device__ __nv_bfloat16 g_w1_hi[(size_t)E * DIM * HID];   // [e][k][n] (orig layout)
__device__ __nv_bfloat16 g_w1_lo[(size_t)E * DIM * HID];
__device__ __nv_bfloat16 g_w2_hi[(size_t)E * HID * DIM];   // [e][k][n]
__device__ __nv_bfloat16 g_w2_lo[(size_t)E * HID * DIM];
__device__ __nv_bfloat16 g_h_hi[(size_t)E * CAP * S * HID];
__device__ __nv_bfloat16 g_h_lo[(size_t)E * CAP * S * HID];

// ---------------- PTX helpers ----------------------------------------------
__device__ __forceinline__ uint32_t smem_u32(const void* p) {
    uint32_t a;
    asm("{ .reg .u64 t; cvta.to.shared.u64 t, %1; cvt.u32.u64 %0, t; }" : "=r"(a) : "l"(p));
    return a;
}
__device__ __forceinline__ void cp16(uint32_t dst, const void* src) {
    asm volatile("cp.async.cg.shared.global [%0], [%1], 16;" :: "r"(dst), "l"(src));
}
#define CP_COMMIT()  asm volatile("cp.async.commit_group;" ::: "memory")
#define CP_WAIT_1()  asm volatile("cp.async.wait_group 1;" ::: "memory")
#define CP_WAIT_0()  asm volatile("cp.async.wait_group 0;" ::: "memory")

__device__ __forceinline__ void ldsm_x4(uint32_t a, uint32_t r[4]) {
    asm volatile("ldmatrix.sync.aligned.m8n8.x4.shared.b16 {%0,%1,%2,%3}, [%4];"
                 : "=r"(r[0]), "=r"(r[1]), "=r"(r[2]), "=r"(r[3]) : "r"(a));
}
__device__ __forceinline__ void ldsm_x4t(uint32_t a, uint32_t r[4]) {
    asm volatile("ldmatrix.sync.aligned.m8n8.x4.trans.shared.b16 {%0,%1,%2,%3}, [%4];"
                 : "=r"(r[0]), "=r"(r[1]), "=r"(r[2]), "=r"(r[3]) : "r"(a));
}
__device__ __forceinline__ void mma16816(float c[4], const uint32_t a[4],
                                         uint32_t b0, uint32_t b1) {
    asm volatile("mma.sync.aligned.m16n8k16.row.col.f32.bf16.bf16.f32 "
                 "{%0,%1,%2,%3},{%4,%5,%6,%7},{%8,%9},{%0,%1,%2,%3};"
                 : "+f"(c[0]), "+f"(c[1]), "+f"(c[2]), "+f"(c[3])
                 : "r"(a[0]), "r"(a[1]), "r"(a[2]), "r"(a[3]), "r"(b0), "r"(b1));
}

// ---------------- kernel: ri = mean over sequence ---------------------------
__global__ void ri_kernel(const float* __restrict__ rin) {
    int idx = blockIdx.x * blockDim.x + threadIdx.x;
    if (idx >= B * DIM) return;
    int b = idx / DIM, d = idx % DIM;
    const float* p = rin + (size_t)b * S * DIM + d;
    float acc = 0.f;
    #pragma unroll 8
    for (int s = 0; s < S; ++s) acc += p[(size_t)s * DIM];
    g_ri[idx] = acc * (1.0f / S);
}

// ---------------- kernel: router + top-2 + capacity -------------------------
__global__ void router_kernel(const float* __restrict__ noise,
                              const float* __restrict__ Wg, const float* __restrict__ bg,
                              const float* __restrict__ Wn, const float* __restrict__ bn) {
    __shared__ float s_noisy[B][E];
    __shared__ int   s_fe[NPAIR];
    __shared__ float s_fg[NPAIR];
    int t = threadIdx.x;
    if (t < B * E) {
        int b = t / E, e = t % E;
        const float* ri = g_ri + b * DIM;
        float lg = 0.f, ln = 0.f;
        for (int d = 0; d < DIM; ++d) {
            float r = ri[d];
            lg = fmaf(r, Wg[d * E + e], lg);
            ln = fmaf(r, Wn[d * E + e], ln);
        }
        lg += bg[e]; ln += bn[e];
        float sp = (ln > 20.f) ? ln : log1pf(expf(ln));
        s_noisy[b][e] = lg + noise[b * E + e] * sp;
    }
    __syncthreads();
    if (t < B) {
        float v1 = -INFINITY; int i1 = -1;
        for (int e = 0; e < E; ++e) { float v = s_noisy[t][e]; if (v > v1) { v1 = v; i1 = e; } }
        float v2 = -INFINITY; int i2 = -1;
        for (int e = 0; e < E; ++e) { if (e == i1) continue; float v = s_noisy[t][e]; if (v > v2) { v2 = v; i2 = e; } }
        float g1 = 1.f / (1.f + expf(v2 - v1));
        s_fe[t * TOPK + 0] = i1; s_fg[t * TOPK + 0] = g1;
        s_fe[t * TOPK + 1] = i2; s_fg[t * TOPK + 1] = 1.f - g1;
    }
    __syncthreads();
    if (t == 0) {
        int cnt[E];
        #pragma unroll
        for (int e = 0; e < E; ++e) cnt[e] = 0;
        for (int p = 0; p < NPAIR; ++p) {
            int e = s_fe[p];
            int c = cnt[e]++;
            if (c < CAP) { g_sample[e * CAP + c] = p / TOPK; g_gate[e * CAP + c] = s_fg[p]; }
        }
        #pragma unroll
        for (int e = 0; e < E; ++e) g_count[e] = (cnt[e] < CAP) ? cnt[e] : CAP;
    }
}

// ---------------- zero output ------------------------------------------------
__global__ void zero_kernel(float4* __restrict__ out) {
    const size_t n4 = (size_t)B * S * DIM / 4;
    size_t i = (size_t)blockIdx.x * blockDim.x + threadIdx.x;
    size_t stride = (size_t)gridDim.x * blockDim.x;
    for (; i < n4; i += stride) out[i] = make_float4(0.f, 0.f, 0.f, 0.f);
}

// ---------------- conversion: fp32 -> bf16 hi/lo -----------------------------
__global__ void conv_split(const float4* __restrict__ in,
                           __nv_bfloat162* __restrict__ oh,
                           __nv_bfloat162* __restrict__ ol, size_t n4) {
    size_t i = (size_t)blockIdx.x * blockDim.x + threadIdx.x;
    size_t stride = (size_t)gridDim.x * blockDim.x;
    for (; i < n4; i += stride) {
        float4 v = in[i];
        __nv_bfloat16 hx = __float2bfloat16(v.x), hy = __float2bfloat16(v.y);
        __nv_bfloat16 hz = __float2bfloat16(v.z), hw = __float2bfloat16(v.w);
        oh[2*i]   = __nv_bfloat162{hx, hy};
        oh[2*i+1] = __nv_bfloat162{hz, hw};
        ol[2*i]   = __nv_bfloat162{__float2bfloat16(v.x - __bfloat162float(hx)),
                                   __float2bfloat16(v.y - __bfloat162float(hy))};
        ol[2*i+1] = __nv_bfloat162{__float2bfloat16(v.z - __bfloat162float(hz)),
                                   __float2bfloat16(v.w - __bfloat162float(hw))};
    }
}

// ---------------- HMMA grouped GEMM ------------------------------------------
// CTA: 256 thr (8 warps as 4M x 2N), tile 128(M) x 128(N), K chunks of 32.
// 3-way bf16 split: Ah*Bh + Ah*Bl + Al*Bh, fp32 register accumulators.
template<bool G1>
__global__ void __launch_bounds__(256, 1) moe_gemm(
    const float* __restrict__ bias, float* __restrict__ out) {
    const int e    = blockIdx.z;
    const int mt   = blockIdx.y;
    const int slot = mt >> 2;
    if (slot >= g_count[e]) return;
    const int token0 = (mt & 3) * 128;
    const int n0     = blockIdx.x * 128;
    const int sample = g_sample[e * CAP + slot];

    const int KS = G1 ? DIM : HID;   // A row length (K)
    const int NS = G1 ? HID : DIM;   // B row length (N)
    const int C  = KS / KC;

    const size_t arow0 = G1 ? ((size_t)sample * S + token0)
                            : ((size_t)(e * CAP + slot) * S + token0);
    const __nv_bfloat16* Ah = (G1 ? g_xc_hi : g_h_hi) + arow0 * KS;
    const __nv_bfloat16* Al = (G1 ? g_xc_lo : g_h_lo) + arow0 * KS;
    const __nv_bfloat16* Bh = (G1 ? g_w1_hi : g_w2_hi) + (size_t)e * KS * NS;
    const __nv_bfloat16* Bl = (G1 ? g_w1_lo : g_w2_lo) + (size_t)e * KS * NS;

    extern __shared__ __align__(128) char smem_raw[];
    const uint32_t sb = smem_u32(smem_raw);
    const int tid = threadIdx.x, w = tid >> 5, lane = tid & 31;
    const int wm = w & 3, wn = w >> 2;

    // ---- chunk loader ----
    auto load_chunk = [&](int c, int s_) {
        const int k0 = c * KC;
        const uint32_t base = sb + s_ * STAGE;
        #pragma unroll
        for (int j = 0; j < 8; ++j) {
            int i = tid + j * 256;
            if (i < 1024) {                    // A: 2(sub) x 128 rows x 4 segs
                int sub = i >> 9, idx = i & 511;
                int row = idx >> 2, seg = idx & 3;
                const __nv_bfloat16* src = (sub ? Al : Ah) + (size_t)row * KS + k0 + seg * 8;
                cp16(base + sub * A_MAT + row * A_STRIDE + seg * 16, src);
            } else {                           // B: 2(sub) x 32 rows x 16 segs
                int j2 = i - 1024;
                int sub = j2 >> 9, idx = j2 & 511;
                int row = idx >> 4, seg = idx & 15;
                const __nv_bfloat16* src = (sub ? Bl : Bh) + (size_t)(k0 + row) * NS + n0 + seg * 8;
                cp16(base + 2 * A_MAT + sub * B_MAT + row * B_STRIDE + seg * 16, src);
            }
        }
        CP_COMMIT();
    };

    float acc[2][8][4];
    #pragma unroll
    for (int mi = 0; mi < 2; ++mi)
        #pragma unroll
        for (int nb = 0; nb < 8; ++nb)
            #pragma unroll
            for (int q = 0; q < 4; ++q) acc[mi][nb][q] = 0.f;

    load_chunk(0, 0);
    load_chunk(1, 1);

    const uint32_t aLane = (wm * 32 + (lane & 15)) * A_STRIDE + (lane >> 4) * 16;
    const uint32_t bLane = 2 * A_MAT + (lane & 15) * B_STRIDE + (wn * 64 + (lane >> 4) * 8) * 2;

    for (int c = 0; c < C; ++c) {
        const int s_ = c & 1;
        if (c + 2 < C) { CP_WAIT_1(); } else { CP_WAIT_0(); }
        __syncthreads();
        const uint32_t base = sb + s_ * STAGE;
        #pragma unroll
        for (int ks = 0; ks < 2; ++ks) {
            uint32_t ah[2][4], al[2][4], bh[4][4], bl[4][4];
            #pragma unroll
            for (int mi = 0; mi < 2; ++mi) {
                uint32_t a = base + aLane + ks * 32 + mi * 16 * A_STRIDE;
                ldsm_x4(a, ah[mi]);
                ldsm_x4(a + A_MAT, al[mi]);
            }
            #pragma unroll
            for (int nb2 = 0; nb2 < 4; ++nb2) {
                uint32_t a = base + bLane + ks * 16 * B_STRIDE + nb2 * 32;
                ldsm_x4t(a, bh[nb2]);
                ldsm_x4t(a + B_MAT, bl[nb2]);
            }
            #pragma unroll
            for (int mi = 0; mi < 2; ++mi)
                #pragma unroll
                for (int nb = 0; nb < 8; ++nb) {
                    const int n2 = nb >> 1, h = (nb & 1) * 2;
                    mma16816(acc[mi][nb], ah[mi], bh[n2][h], bh[n2][h + 1]);
                    mma16816(acc[mi][nb], ah[mi], bl[n2][h], bl[n2][h + 1]);
                    mma16816(acc[mi][nb], al[mi], bh[n2][h], bh[n2][h + 1]);
                }
        }
        __syncthreads();
        if (c + 2 < C) load_chunk(c + 2, s_);
    }

    // ---- epilogue ----
    const int rbase = wm * 32 + (lane >> 2);
    const float gate = G1 ? 0.f : g_gate[e * CAP + slot];
    #pragma unroll
    for (int mi = 0; mi < 2; ++mi) {
        #pragma unroll
        for (int nb = 0; nb < 8; ++nb) {
            const int nc = wn * 64 + nb * 8 + (lane & 3) * 2;
            const float bx = bias[(size_t)e * NS + n0 + nc];
            const float by = bias[(size_t)e * NS + n0 + nc + 1];
            #pragma unroll
            for (int rr = 0; rr < 2; ++rr) {
                const int row = rbase + mi * 16 + rr * 8;
                float v0 = acc[mi][nb][rr * 2 + 0] + bx;
                float v1 = acc[mi][nb][rr * 2 + 1] + by;
                if (G1) {
                    v0 = 0.5f * v0 * (1.0f + erff(v0 * 0.70710678118654752f));
                    v1 = 0.5f * v1 * (1.0f + erff(v1 * 0.70710678118654752f));
                    __nv_bfloat16 h0 = __float2bfloat16(v0), h1 = __float2bfloat16(v1);
                    size_t off = ((size_t)(e * CAP + slot) * S + token0 + row) * HID + n0 + nc;
                    *reinterpret_cast<__nv_bfloat162*>(g_h_hi + off) = __nv_bfloat162{h0, h1};
                    *reinterpret_cast<__nv_bfloat162*>(g_h_lo + off) = __nv_bfloat162{
                        __float2bfloat16(v0 - __bfloat162float(h0)),
                        __float2bfloat16(v1 - __bfloat162float(h1))};
                } else {
                    float* dst = out + ((size_t)sample * S + token0 + row) * DIM + n0 + nc;
                    atomicAdd(dst + 0, v0 * gate);
                    atomicAdd(dst + 1, v1 * gate);
                }
            }
        }
    }
}

// ---------------- launch ------------------------------------------------------
extern "C" void kernel_launch(void* const* d_in, const int* in_sizes, int n_in,
                              void* d_out, int out_size) {
    const float* rin   = (const float*)d_in[0];
    const float* x     = (const float*)d_in[1];
    const float* noise = (const float*)d_in[2];
    const float* Wg    = (const float*)d_in[3];
    const float* bg    = (const float*)d_in[4];
    const float* Wn    = (const float*)d_in[5];
    const float* bn    = (const float*)d_in[6];
    const float* W1    = (const float*)d_in[7];
    const float* b1    = (const float*)d_in[8];
    const float* W2    = (const float*)d_in[9];
    const float* b2    = (const float*)d_in[10];
    float* out = (float*)d_out;

    cudaFuncSetAttribute(moe_gemm<true>,  cudaFuncAttributeMaxDynamicSharedMemorySize, SMEM_DYN);
    cudaFuncSetAttribute(moe_gemm<false>, cudaFuncAttributeMaxDynamicSharedMemorySize, SMEM_DYN);

    ri_kernel<<<(B * DIM + 255) / 256, 256>>>(rin);
    router_kernel<<<1, 256>>>(noise, Wg, bg, Wn, bn);
    zero_kernel<<<2048, 256>>>(reinterpret_cast<float4*>(out));

    __nv_bfloat162 *xh, *xl, *w1h, *w1l, *w2h, *w2l;
    cudaGetSymbolAddress((void**)&xh,  g_xc_hi);
    cudaGetSymbolAddress((void**)&xl,  g_xc_lo);
    cudaGetSymbolAddress((void**)&w1h, g_w1_hi);
    cudaGetSymbolAddress((void**)&w1l, g_w1_lo);
    cudaGetSymbolAddress((void**)&w2h, g_w2_hi);
    cudaGetSymbolAddress((void**)&w2l, g_w2_lo);

    conv_split<<<4096, 256>>>((const float4*)x,  xh,  xl,  (size_t)B * S * DIM / 4);
    conv_split<<<8192, 256>>>((const float4*)W1, w1h, w1l, (size_t)E * DIM * HID / 4);
    conv_split<<<8192, 256>>>((const float4*)W2, w2h, w2l, (size_t)E * HID * DIM / 4);

    moe_gemm<true ><<<dim3(HID / 128, 32, E), 256, SMEM_DYN>>>(b1, out);
    moe_gemm<false><<<dim3(DIM / 128, 32, E), 256, SMEM_DYN>>>(b2, out);
}

// round 4
// speedup vs baseline: 3.0021x; 1.3515x over previous
#include <cuda_runtime.h>
#include <cuda_bf16.h>
#include <math.h>
#include <stdint.h>

#define B    32
#define S    512
#define DIM  1024
#define HID  4096
#define E    8
#define TOPK 2
#define CAP  8
#define NPAIR (B*TOPK)

#define KC   32                 // K chunk (bf16 elems)
#define NT   256                // N tile
#define A_STRIDE 80             // bytes per A row in smem
#define B_STRIDE 528            // bytes per B row in smem (256*2 padded)
#define A_MAT   10240           // 128 rows * 80B
#define B_MAT   16896           // 32 rows * 528B
#define A_SZ    20480           // 2 * A_MAT
#define STAGE   54272           // A hi/lo + B hi/lo
#define NSTAGE  4
#define SMEM_DYN (NSTAGE * STAGE)

// ---------------- device scratch -------------------------------------------
__device__ float g_ri[B * DIM];
__device__ int   g_sample[E * CAP];
__device__ float g_gate[E * CAP];
__device__ int   g_count[E];
__device__ __nv_bfloat16 g_xc_hi[(size_t)B * S * DIM];
__device__ __nv_bfloat16 g_xc_lo[(size_t)B * S * DIM];
__device__ __nv_bfloat16 g_w1_hi[(size_t)E * DIM * HID];   // [e][k][n]
__device__ __nv_bfloat16 g_w1_lo[(size_t)E * DIM * HID];
__device__ __nv_bfloat16 g_w2_hi[(size_t)E * HID * DIM];   // [e][k][n]
__device__ __nv_bfloat16 g_w2_lo[(size_t)E * HID * DIM];
__device__ __nv_bfloat16 g_h_hi[(size_t)E * CAP * S * HID];
__device__ __nv_bfloat16 g_h_lo[(size_t)E * CAP * S * HID];

// ---------------- PTX helpers ----------------------------------------------
__device__ __forceinline__ uint32_t smem_u32(const void* p) {
    uint32_t a;
    asm("{ .reg .u64 t; cvta.to.shared.u64 t, %1; cvt.u32.u64 %0, t; }" : "=r"(a) : "l"(p));
    return a;
}
__device__ __forceinline__ void cp16(uint32_t dst, const void* src) {
    asm volatile("cp.async.cg.shared.global [%0], [%1], 16;" :: "r"(dst), "l"(src));
}
#define CP_COMMIT()  asm volatile("cp.async.commit_group;" ::: "memory")
#define CP_WAIT_2()  asm volatile("cp.async.wait_group 2;" ::: "memory")
#define CP_WAIT_1()  asm volatile("cp.async.wait_group 1;" ::: "memory")
#define CP_WAIT_0()  asm volatile("cp.async.wait_group 0;" ::: "memory")

__device__ __forceinline__ void ldsm_x4(uint32_t a, uint32_t r[4]) {
    asm volatile("ldmatrix.sync.aligned.m8n8.x4.shared.b16 {%0,%1,%2,%3}, [%4];"
                 : "=r"(r[0]), "=r"(r[1]), "=r"(r[2]), "=r"(r[3]) : "r"(a));
}
__device__ __forceinline__ void ldsm_x4t(uint32_t a, uint32_t r[4]) {
    asm volatile("ldmatrix.sync.aligned.m8n8.x4.trans.shared.b16 {%0,%1,%2,%3}, [%4];"
                 : "=r"(r[0]), "=r"(r[1]), "=r"(r[2]), "=r"(r[3]) : "r"(a));
}
__device__ __forceinline__ void mma16816(float c[4], const uint32_t a[4],
                                         uint32_t b0, uint32_t b1) {
    asm volatile("mma.sync.aligned.m16n8k16.row.col.f32.bf16.bf16.f32 "
                 "{%0,%1,%2,%3},{%4,%5,%6,%7},{%8,%9},{%0,%1,%2,%3};"
                 : "+f"(c[0]), "+f"(c[1]), "+f"(c[2]), "+f"(c[3])
                 : "r"(a[0]), "r"(a[1]), "r"(a[2]), "r"(a[3]), "r"(b0), "r"(b1));
}

// ---------------- kernel: ri = mean over sequence ---------------------------
__global__ void ri_kernel(const float* __restrict__ rin) {
    int idx = blockIdx.x * blockDim.x + threadIdx.x;
    if (idx >= B * DIM) return;
    int b = idx / DIM, d = idx % DIM;
    const float* p = rin + (size_t)b * S * DIM + d;
    float acc = 0.f;
    #pragma unroll 8
    for (int s = 0; s < S; ++s) acc += p[(size_t)s * DIM];
    g_ri[idx] = acc * (1.0f / S);
}

// ---------------- kernel: router + top-2 + capacity -------------------------
__global__ void router_kernel(const float* __restrict__ noise,
                              const float* __restrict__ Wg, const float* __restrict__ bg,
                              const float* __restrict__ Wn, const float* __restrict__ bn) {
    __shared__ float s_noisy[B][E];
    __shared__ int   s_fe[NPAIR];
    __shared__ float s_fg[NPAIR];
    int t = threadIdx.x;
    if (t < B * E) {
        int b = t / E, e = t % E;
        const float* ri = g_ri + b * DIM;
        float lg = 0.f, ln = 0.f;
        for (int d = 0; d < DIM; ++d) {
            float r = ri[d];
            lg = fmaf(r, Wg[d * E + e], lg);
            ln = fmaf(r, Wn[d * E + e], ln);
        }
        lg += bg[e]; ln += bn[e];
        float sp = (ln > 20.f) ? ln : log1pf(expf(ln));
        s_noisy[b][e] = lg + noise[b * E + e] * sp;
    }
    __syncthreads();
    if (t < B) {
        float v1 = -INFINITY; int i1 = -1;
        for (int e = 0; e < E; ++e) { float v = s_noisy[t][e]; if (v > v1) { v1 = v; i1 = e; } }
        float v2 = -INFINITY; int i2 = -1;
        for (int e = 0; e < E; ++e) { if (e == i1) continue; float v = s_noisy[t][e]; if (v > v2) { v2 = v; i2 = e; } }
        float g1 = 1.f / (1.f + expf(v2 - v1));
        s_fe[t * TOPK + 0] = i1; s_fg[t * TOPK + 0] = g1;
        s_fe[t * TOPK + 1] = i2; s_fg[t * TOPK + 1] = 1.f - g1;
    }
    __syncthreads();
    if (t == 0) {
        int cnt[E];
        #pragma unroll
        for (int e = 0; e < E; ++e) cnt[e] = 0;
        for (int p = 0; p < NPAIR; ++p) {
            int e = s_fe[p];
            int c = cnt[e]++;
            if (c < CAP) { g_sample[e * CAP + c] = p / TOPK; g_gate[e * CAP + c] = s_fg[p]; }
        }
        #pragma unroll
        for (int e = 0; e < E; ++e) g_count[e] = (cnt[e] < CAP) ? cnt[e] : CAP;
    }
}

// ---------------- zero output ------------------------------------------------
__global__ void zero_kernel(float4* __restrict__ out) {
    const size_t n4 = (size_t)B * S * DIM / 4;
    size_t i = (size_t)blockIdx.x * blockDim.x + threadIdx.x;
    size_t stride = (size_t)gridDim.x * blockDim.x;
    for (; i < n4; i += stride) out[i] = make_float4(0.f, 0.f, 0.f, 0.f);
}

// ---------------- conversion: fp32 -> bf16 hi/lo -----------------------------
__global__ void conv_split(const float4* __restrict__ in,
                           __nv_bfloat162* __restrict__ oh,
                           __nv_bfloat162* __restrict__ ol, size_t n4) {
    size_t i = (size_t)blockIdx.x * blockDim.x + threadIdx.x;
    size_t stride = (size_t)gridDim.x * blockDim.x;
    for (; i < n4; i += stride) {
        float4 v = in[i];
        __nv_bfloat16 hx = __float2bfloat16(v.x), hy = __float2bfloat16(v.y);
        __nv_bfloat16 hz = __float2bfloat16(v.z), hw = __float2bfloat16(v.w);
        oh[2*i]   = __nv_bfloat162{hx, hy};
        oh[2*i+1] = __nv_bfloat162{hz, hw};
        ol[2*i]   = __nv_bfloat162{__float2bfloat16(v.x - __bfloat162float(hx)),
                                   __float2bfloat16(v.y - __bfloat162float(hy))};
        ol[2*i+1] = __nv_bfloat162{__float2bfloat16(v.z - __bfloat162float(hz)),
                                   __float2bfloat16(v.w - __bfloat162float(hw))};
    }
}

// ---------------- HMMA grouped GEMM ------------------------------------------
// CTA: 512 thr (16 warps as 4M x 4N), tile 128(M) x 256(N), K chunks of 32,
// 4-stage cp.async pipeline, one __syncthreads per iteration.
// 3-way bf16 split: Ah*Bh + Ah*Bl + Al*Bh, fp32 register accumulators.
template<bool G1>
__global__ void __launch_bounds__(512, 1) moe_gemm(
    const float* __restrict__ bias, float* __restrict__ out) {
    const int e    = blockIdx.z;
    const int mt   = blockIdx.y;
    const int slot = mt >> 2;
    if (slot >= g_count[e]) return;
    const int token0 = (mt & 3) * 128;
    const int n0     = blockIdx.x * NT;
    const int sample = g_sample[e * CAP + slot];

    const int KS = G1 ? DIM : HID;   // A row length (K)
    const int NS = G1 ? HID : DIM;   // B row length (N)
    const int C  = KS / KC;

    const size_t arow0 = G1 ? ((size_t)sample * S + token0)
                            : ((size_t)(e * CAP + slot) * S + token0);
    const __nv_bfloat16* Ah = (G1 ? g_xc_hi : g_h_hi) + arow0 * KS;
    const __nv_bfloat16* Al = (G1 ? g_xc_lo : g_h_lo) + arow0 * KS;
    const __nv_bfloat16* Bh = (G1 ? g_w1_hi : g_w2_hi) + (size_t)e * KS * NS;
    const __nv_bfloat16* Bl = (G1 ? g_w1_lo : g_w2_lo) + (size_t)e * KS * NS;

    extern __shared__ __align__(128) char smem_raw[];
    const uint32_t sb = smem_u32(smem_raw);
    const int tid = threadIdx.x, w = tid >> 5, lane = tid & 31;
    const int wm = w & 3, wn = w >> 2;

    // ---- chunk loader: 3072 cp16 ops (A 1024, B 2048), 6 per thread --------
    auto load_chunk = [&](int c, int s_) {
        const int k0 = c * KC;
        const uint32_t base = sb + s_ * STAGE;
        #pragma unroll
        for (int j = 0; j < 6; ++j) {
            int i = tid + j * 512;
            if (i < 1024) {                    // A: 2(sub) x 128 rows x 4 segs
                int sub = i >> 9, idx = i & 511;
                int row = idx >> 2, seg = idx & 3;
                const __nv_bfloat16* src = (sub ? Al : Ah) + (size_t)row * KS + k0 + seg * 8;
                cp16(base + sub * A_MAT + row * A_STRIDE + seg * 16, src);
            } else {                           // B: 2(sub) x 32 rows x 32 segs
                int j2 = i - 1024;
                int sub = j2 >> 10, idx = j2 & 1023;
                int row = idx >> 5, seg = idx & 31;
                const __nv_bfloat16* src = (sub ? Bl : Bh) + (size_t)(k0 + row) * NS + n0 + seg * 8;
                cp16(base + A_SZ + sub * B_MAT + row * B_STRIDE + seg * 16, src);
            }
        }
        CP_COMMIT();
    };

    float acc[2][8][4];
    #pragma unroll
    for (int mi = 0; mi < 2; ++mi)
        #pragma unroll
        for (int nb = 0; nb < 8; ++nb)
            #pragma unroll
            for (int q = 0; q < 4; ++q) acc[mi][nb][q] = 0.f;

    load_chunk(0, 0);
    load_chunk(1, 1);
    load_chunk(2, 2);

    const uint32_t aLane = (wm * 32 + (lane & 15)) * A_STRIDE + (lane >> 4) * 16;
    const uint32_t bLane = A_SZ + (lane & 15) * B_STRIDE + (wn * 64 + (lane >> 4) * 8) * 2;

    for (int c = 0; c < C; ++c) {
        const int s_ = c & (NSTAGE - 1);
        if (c <= C - 3)      { CP_WAIT_2(); }
        else if (c == C - 2) { CP_WAIT_1(); }
        else                 { CP_WAIT_0(); }
        __syncthreads();
        const uint32_t base = sb + s_ * STAGE;
        #pragma unroll
        for (int ks = 0; ks < 2; ++ks) {
            uint32_t ah[2][4], al[2][4];
            #pragma unroll
            for (int mi = 0; mi < 2; ++mi) {
                uint32_t a = base + aLane + ks * 32 + mi * 16 * A_STRIDE;
                ldsm_x4(a, ah[mi]);
                ldsm_x4(a + A_MAT, al[mi]);
            }
            #pragma unroll
            for (int nb2 = 0; nb2 < 4; ++nb2) {
                uint32_t bh[4], bl[4];
                uint32_t a = base + bLane + ks * 16 * B_STRIDE + nb2 * 32;
                ldsm_x4t(a, bh);
                ldsm_x4t(a + B_MAT, bl);
                #pragma unroll
                for (int mi = 0; mi < 2; ++mi)
                    #pragma unroll
                    for (int h = 0; h < 2; ++h) {
                        float* ac = acc[mi][nb2 * 2 + h];
                        mma16816(ac, ah[mi], bh[h * 2], bh[h * 2 + 1]);
                        mma16816(ac, ah[mi], bl[h * 2], bl[h * 2 + 1]);
                        mma16816(ac, al[mi], bh[h * 2], bh[h * 2 + 1]);
                    }
            }
        }
        if (c + 3 < C) load_chunk(c + 3, (c + 3) & (NSTAGE - 1));
    }

    // ---- epilogue ----
    const int rbase = wm * 32 + (lane >> 2);
    const float gate = G1 ? 0.f : g_gate[e * CAP + slot];
    #pragma unroll
    for (int mi = 0; mi < 2; ++mi) {
        #pragma unroll
        for (int nb = 0; nb < 8; ++nb) {
            const int nc = wn * 64 + nb * 8 + (lane & 3) * 2;
            const float bx = bias[(size_t)e * NS + n0 + nc];
            const float by = bias[(size_t)e * NS + n0 + nc + 1];
            #pragma unroll
            for (int rr = 0; rr < 2; ++rr) {
                const int row = rbase + mi * 16 + rr * 8;
                float v0 = acc[mi][nb][rr * 2 + 0] + bx;
                float v1 = acc[mi][nb][rr * 2 + 1] + by;
                if (G1) {
                    v0 = 0.5f * v0 * (1.0f + erff(v0 * 0.70710678118654752f));
                    v1 = 0.5f * v1 * (1.0f + erff(v1 * 0.70710678118654752f));
                    __nv_bfloat16 h0 = __float2bfloat16(v0), h1 = __float2bfloat16(v1);
                    size_t off = ((size_t)(e * CAP + slot) * S + token0 + row) * HID + n0 + nc;
                    *reinterpret_cast<__nv_bfloat162*>(g_h_hi + off) = __nv_bfloat162{h0, h1};
                    *reinterpret_cast<__nv_bfloat162*>(g_h_lo + off) = __nv_bfloat162{
                        __float2bfloat16(v0 - __bfloat162float(h0)),
                        __float2bfloat16(v1 - __bfloat162float(h1))};
                } else {
                    float* dst = out + ((size_t)sample * S + token0 + row) * DIM + n0 + nc;
                    atomicAdd(dst + 0, v0 * gate);
                    atomicAdd(dst + 1, v1 * gate);
                }
            }
        }
    }
}

// ---------------- launch ------------------------------------------------------
extern "C" void kernel_launch(void* const* d_in, const int* in_sizes, int n_in,
                              void* d_out, int out_size) {
    const float* rin   = (const float*)d_in[0];
    const float* x     = (const float*)d_in[1];
    const float* noise = (const float*)d_in[2];
    const float* Wg    = (const float*)d_in[3];
    const float* bg    = (const float*)d_in[4];
    const float* Wn    = (const float*)d_in[5];
    const float* bn    = (const float*)d_in[6];
    const float* W1    = (const float*)d_in[7];
    const float* b1    = (const float*)d_in[8];
    const float* W2    = (const float*)d_in[9];
    const float* b2    = (const float*)d_in[10];
    float* out = (float*)d_out;

    cudaFuncSetAttribute(moe_gemm<true>,  cudaFuncAttributeMaxDynamicSharedMemorySize, SMEM_DYN);
    cudaFuncSetAttribute(moe_gemm<false>, cudaFuncAttributeMaxDynamicSharedMemorySize, SMEM_DYN);

    ri_kernel<<<(B * DIM + 255) / 256, 256>>>(rin);
    router_kernel<<<1, 256>>>(noise, Wg, bg, Wn, bn);
    zero_kernel<<<2048, 256>>>(reinterpret_cast<float4*>(out));

    __nv_bfloat162 *xh, *xl, *w1h, *w1l, *w2h, *w2l;
    cudaGetSymbolAddress((void**)&xh,  g_xc_hi);
    cudaGetSymbolAddress((void**)&xl,  g_xc_lo);
    cudaGetSymbolAddress((void**)&w1h, g_w1_hi);
    cudaGetSymbolAddress((void**)&w1l, g_w1_lo);
    cudaGetSymbolAddress((void**)&w2h, g_w2_hi);
    cudaGetSymbolAddress((void**)&w2l, g_w2_lo);

    conv_split<<<4096, 256>>>((const float4*)x,  xh,  xl,  (size_t)B * S * DIM / 4);
    conv_split<<<8192, 256>>>((const float4*)W1, w1h, w1l, (size_t)E * DIM * HID / 4);
    conv_split<<<8192, 256>>>((const float4*)W2, w2h, w2l, (size_t)E * HID * DIM / 4);

    moe_gemm<true ><<<dim3(HID / NT, 32, E), 512, SMEM_DYN>>>(b1, out);
    moe_gemm<false><<<dim3(DIM / NT, 32, E), 512, SMEM_DYN>>>(b2, out);
}